// round 7
// baseline (speedup 1.0000x reference)
#include <cuda_runtime.h>
#include <math.h>

#define N_NODES 30000
#define N_EDGES 480000
#define E_TOT   (N_EDGES + N_NODES)   // 510000 (self-loops appended)
#define NEG_SLOPE 0.2f

// ---------------- device scratch (static, no allocation) ----------------
__device__ int   g_flag32;                 // 1 => edge_index is int32
__device__ int   g_deg[N_NODES];
__device__ int   g_rowptr[N_NODES + 1];
__device__ int   g_src[E_TOT];
__device__ int   g_dst[E_TOT];
__device__ int   g_rank[E_TOT];
__device__ int   g_srcsorted[E_TOT];
__device__ float g_h1[N_NODES * 128];
__device__ float g_as1[N_NODES * 8];
__device__ float g_ad1[N_NODES * 8];
__device__ float g_x2[N_NODES * 128];
__device__ float g_h2[N_NODES * 64];
__device__ float g_as2[N_NODES];
__device__ float g_ad2[N_NODES];

// GEMM1: 64 nodes per block
#define G1_MB     64
#define G1_BLOCKS ((N_NODES + G1_MB - 1) / G1_MB)   // 469
#define G1_A      (G1_BLOCKS / 2)                   // 234 (with convert)
#define G1_B      (G1_BLOCKS - G1_A)                // 235 (with scatter)
#define NCONV     ((E_TOT + 255) / 256)             // 1993

// ---------------- edge dtype detection (sampled, 1 block) ----------------
// int64: odd 32-bit words are high halves of values < 30000 -> all zero.
// int32: odd words are random node indices -> some nonzero among 2048 samples.
__global__ void k_detect(const unsigned int* __restrict__ w) {
    unsigned int acc = 0;
#pragma unroll
    for (int k = 0; k < 8; k++) {
        int s = threadIdx.x * 8 + k;          // 0..2047
        acc |= w[2 * (s * 234) + 1];          // max index 957997 < 960000
    }
    if (acc) atomicOr(&g_flag32, 1);
}

// ---------------- GEMM body (shared by fused + standalone kernels) -------
// H[M,NOUT] = X[M,128] @ W[128,NOUT]; fused alpha epilogue.
// k-loop vectorized by 4; NPT=8 rows/thread so 4 W-row loads feed 128 FFMA.
template <int NOUT, int TY, int NPT, int HEADS>
__device__ __forceinline__ void gemm_body(
    int bid, int tid,
    const float* __restrict__ X, const float* __restrict__ W,
    float* __restrict__ H,
    const float* __restrict__ asrc, const float* __restrict__ adst,
    float* __restrict__ as_out, float* __restrict__ ad_out,
    float (*xs)[128]) {
    constexpr int K  = 128;
    constexpr int TX = NOUT / 4;
    constexpr int MB = TY * NPT;
    constexpr int G  = TX / HEADS;
    int tx = tid % TX, ty = tid / TX;

    int tile0 = bid * MB;
    constexpr int NLOAD = MB * K / 4;
    for (int idx = tid; idx < NLOAD; idx += TX * TY) {
        int r = idx / (K / 4), c = idx % (K / 4);
        float4 v = make_float4(0.f, 0.f, 0.f, 0.f);
        int node = tile0 + r;
        if (node < N_NODES) v = ((const float4*)X)[node * (K / 4) + c];
        *(float4*)&xs[r][c * 4] = v;
    }
    __syncthreads();

    float4 acc[NPT];
#pragma unroll
    for (int p = 0; p < NPT; p++) acc[p] = make_float4(0.f, 0.f, 0.f, 0.f);
    int jx = tx * 4;
    const float* Wp = W + jx;

#pragma unroll 2
    for (int k4 = 0; k4 < K / 4; k4++) {
        float4 w0 = *(const float4*)(Wp + (4 * k4 + 0) * NOUT);
        float4 w1 = *(const float4*)(Wp + (4 * k4 + 1) * NOUT);
        float4 w2 = *(const float4*)(Wp + (4 * k4 + 2) * NOUT);
        float4 w3 = *(const float4*)(Wp + (4 * k4 + 3) * NOUT);
#pragma unroll
        for (int p = 0; p < NPT; p++) {
            float4 xv = *(const float4*)&xs[ty * NPT + p][4 * k4];
            acc[p].x += w0.x * xv.x; acc[p].y += w0.y * xv.x;
            acc[p].z += w0.z * xv.x; acc[p].w += w0.w * xv.x;
            acc[p].x += w1.x * xv.y; acc[p].y += w1.y * xv.y;
            acc[p].z += w1.z * xv.y; acc[p].w += w1.w * xv.y;
            acc[p].x += w2.x * xv.z; acc[p].y += w2.y * xv.z;
            acc[p].z += w2.z * xv.z; acc[p].w += w2.w * xv.z;
            acc[p].x += w3.x * xv.w; acc[p].y += w3.y * xv.w;
            acc[p].z += w3.z * xv.w; acc[p].w += w3.w * xv.w;
        }
    }

    float4 av = *(const float4*)&asrc[jx];
    float4 bv = *(const float4*)&adst[jx];
    int head = tx / G;
#pragma unroll
    for (int p = 0; p < NPT; p++) {
        int node = tile0 + ty * NPT + p;
        if (node < N_NODES) *(float4*)&H[node * NOUT + jx] = acc[p];
        float s = acc[p].x * av.x + acc[p].y * av.y + acc[p].z * av.z + acc[p].w * av.w;
        float d = acc[p].x * bv.x + acc[p].y * bv.y + acc[p].z * bv.z + acc[p].w * bv.w;
#pragma unroll
        for (int o = 1; o < G; o <<= 1) {
            s += __shfl_xor_sync(0xffffffffu, s, o);
            d += __shfl_xor_sync(0xffffffffu, d, o);
        }
        if ((tx % G) == 0 && node < N_NODES) {
            as_out[node * HEADS + head] = s;
            ad_out[node * HEADS + head] = d;
        }
    }
}

// ---------------- fused: convert (+histogram+rank) || gemm1 first half ----
__global__ __launch_bounds__(256)
void k_convert_gemmA(const void* __restrict__ edges,
                     const float* __restrict__ X, const float* __restrict__ W,
                     float* __restrict__ H,
                     const float* __restrict__ asrc, const float* __restrict__ adst,
                     float* __restrict__ as_out, float* __restrict__ ad_out) {
    __shared__ float xs[G1_MB][128];
    if ((int)blockIdx.x < G1_A) {
        gemm_body<128, 8, 8, 8>(blockIdx.x, threadIdx.x, X, W, H,
                                asrc, adst, as_out, ad_out, xs);
        return;
    }
    int i = (blockIdx.x - G1_A) * 256 + threadIdx.x;
    if (i >= E_TOT) return;
    int s, d;
    if (i < N_EDGES) {
        if (g_flag32) {
            const int* p = (const int*)edges;
            s = p[i]; d = p[N_EDGES + i];
        } else {
            const long long* p = (const long long*)edges;
            s = (int)p[i]; d = (int)p[N_EDGES + i];
        }
    } else {
        s = d = i - N_EDGES;
    }
    g_src[i] = s; g_dst[i] = d;
    g_rank[i] = atomicAdd(&g_deg[d], 1);
}

// single-block exclusive scan (30000 elements)
__global__ void k_scan() {
    __shared__ int ss[1024];
    const int CH = (N_NODES + 1023) / 1024;   // 30
    int t = threadIdx.x;
    int base = t * CH;
    int s = 0;
    for (int i = 0; i < CH; i++) {
        int idx = base + i;
        if (idx < N_NODES) s += g_deg[idx];
    }
    ss[t] = s;
    __syncthreads();
    for (int off = 1; off < 1024; off <<= 1) {
        int v = (t >= off) ? ss[t - off] : 0;
        __syncthreads();
        ss[t] += v;
        __syncthreads();
    }
    int run = (t == 0) ? 0 : ss[t - 1];
    for (int i = 0; i < CH; i++) {
        int idx = base + i;
        if (idx < N_NODES) {
            g_rowptr[idx] = run;
            run += g_deg[idx];
        }
    }
    if (t == 0) g_rowptr[N_NODES] = E_TOT;
}

// ---------------- fused: atomic-free scatter || gemm1 second half ---------
__global__ __launch_bounds__(256)
void k_scatter_gemmB(const float* __restrict__ X, const float* __restrict__ W,
                     float* __restrict__ H,
                     const float* __restrict__ asrc, const float* __restrict__ adst,
                     float* __restrict__ as_out, float* __restrict__ ad_out) {
    __shared__ float xs[G1_MB][128];
    if ((int)blockIdx.x < G1_B) {
        gemm_body<128, 8, 8, 8>(G1_A + blockIdx.x, threadIdx.x, X, W, H,
                                asrc, adst, as_out, ad_out, xs);
        return;
    }
    int i = (blockIdx.x - G1_B) * 256 + threadIdx.x;
    if (i >= E_TOT) return;
    g_srcsorted[g_rowptr[g_dst[i]] + g_rank[i]] = g_src[i];
}

// ---------------- standalone gemm2 (128 threads, MB=64, 32KB smem) --------
__global__ __launch_bounds__(128)
void k_gemm2(const float* __restrict__ X, const float* __restrict__ W,
             float* __restrict__ H,
             const float* __restrict__ asrc, const float* __restrict__ adst,
             float* __restrict__ as_out, float* __restrict__ ad_out) {
    __shared__ float xs[64][128];
    gemm_body<64, 8, 8, 1>(blockIdx.x, threadIdx.x, X, W, H,
                           asrc, adst, as_out, ad_out, xs);
}

// ---------------- layer-1: single-pass softmax + aggregate (warp per dst) -
__global__ void k_agg1(const float* __restrict__ b1) {
    int gw = (blockIdx.x * blockDim.x + threadIdx.x) >> 5;
    int lane = threadIdx.x & 31;
    if (gw >= N_NODES) return;
    int beg = g_rowptr[gw], end = g_rowptr[gw + 1];
    int head = lane >> 2;                 // 4 lanes per head (16 cols/head)
    int col = lane * 4;
    float ad = g_ad1[gw * 8 + head];

    float4 acc = make_float4(0.f, 0.f, 0.f, 0.f);
    float sm = 0.f;
    int e = beg;
    for (; e + 3 < end; e += 4) {
        int s0 = g_srcsorted[e], s1 = g_srcsorted[e + 1];
        int s2 = g_srcsorted[e + 2], s3 = g_srcsorted[e + 3];
        float a0 = g_as1[s0 * 8 + head], a1 = g_as1[s1 * 8 + head];
        float a2 = g_as1[s2 * 8 + head], a3 = g_as1[s3 * 8 + head];
        float4 h0 = *(const float4*)&g_h1[s0 * 128 + col];
        float4 h1v = *(const float4*)&g_h1[s1 * 128 + col];
        float4 h2v = *(const float4*)&g_h1[s2 * 128 + col];
        float4 h3 = *(const float4*)&g_h1[s3 * 128 + col];
        float v0 = a0 + ad; v0 = v0 > 0.f ? v0 : NEG_SLOPE * v0;
        float v1 = a1 + ad; v1 = v1 > 0.f ? v1 : NEG_SLOPE * v1;
        float v2 = a2 + ad; v2 = v2 > 0.f ? v2 : NEG_SLOPE * v2;
        float v3 = a3 + ad; v3 = v3 > 0.f ? v3 : NEG_SLOPE * v3;
        float w0 = __expf(v0), w1 = __expf(v1), w2 = __expf(v2), w3 = __expf(v3);
        sm += (w0 + w1) + (w2 + w3);
        acc.x += w0 * h0.x + w1 * h1v.x + w2 * h2v.x + w3 * h3.x;
        acc.y += w0 * h0.y + w1 * h1v.y + w2 * h2v.y + w3 * h3.y;
        acc.z += w0 * h0.z + w1 * h1v.z + w2 * h2v.z + w3 * h3.z;
        acc.w += w0 * h0.w + w1 * h1v.w + w2 * h2v.w + w3 * h3.w;
    }
    for (; e < end; e++) {
        int s = g_srcsorted[e];
        float a = g_as1[s * 8 + head];
        float4 hv = *(const float4*)&g_h1[s * 128 + col];
        float v = a + ad; v = v > 0.f ? v : NEG_SLOPE * v;
        float w = __expf(v);
        sm += w;
        acc.x += w * hv.x; acc.y += w * hv.y;
        acc.z += w * hv.z; acc.w += w * hv.w;
    }

    float inv = 1.f / (sm + 1e-16f);
    float4 bb = *(const float4*)&b1[col];
    float o0 = acc.x * inv + bb.x, o1 = acc.y * inv + bb.y;
    float o2 = acc.z * inv + bb.z, o3 = acc.w * inv + bb.w;
    o0 = o0 > 0.f ? o0 : expm1f(o0);
    o1 = o1 > 0.f ? o1 : expm1f(o1);
    o2 = o2 > 0.f ? o2 : expm1f(o2);
    o3 = o3 > 0.f ? o3 : expm1f(o3);
    *(float4*)&g_x2[gw * 128 + col] = make_float4(o0, o1, o2, o3);
}

// ---------------- layer-2: single-pass softmax + aggregate + log_softmax --
__global__ void k_agg2(const float* __restrict__ b2, float* __restrict__ out) {
    int gw = (blockIdx.x * blockDim.x + threadIdx.x) >> 5;
    int lane = threadIdx.x & 31;
    if (gw >= N_NODES) return;
    int beg = g_rowptr[gw], end = g_rowptr[gw + 1];
    float ad = g_ad2[gw];
    int col = lane * 2;

    float a0 = 0.f, a1 = 0.f, sm = 0.f;
    int e = beg;
    for (; e + 3 < end; e += 4) {
        int s0 = g_srcsorted[e], s1 = g_srcsorted[e + 1];
        int s2 = g_srcsorted[e + 2], s3 = g_srcsorted[e + 3];
        float x0 = g_as2[s0], x1 = g_as2[s1], x2 = g_as2[s2], x3 = g_as2[s3];
        float2 h0 = *(const float2*)&g_h2[s0 * 64 + col];
        float2 h1v = *(const float2*)&g_h2[s1 * 64 + col];
        float2 h2v = *(const float2*)&g_h2[s2 * 64 + col];
        float2 h3 = *(const float2*)&g_h2[s3 * 64 + col];
        float v0 = x0 + ad; v0 = v0 > 0.f ? v0 : NEG_SLOPE * v0;
        float v1 = x1 + ad; v1 = v1 > 0.f ? v1 : NEG_SLOPE * v1;
        float v2 = x2 + ad; v2 = v2 > 0.f ? v2 : NEG_SLOPE * v2;
        float v3 = x3 + ad; v3 = v3 > 0.f ? v3 : NEG_SLOPE * v3;
        float w0 = __expf(v0), w1 = __expf(v1), w2 = __expf(v2), w3 = __expf(v3);
        sm += (w0 + w1) + (w2 + w3);
        a0 += w0 * h0.x + w1 * h1v.x + w2 * h2v.x + w3 * h3.x;
        a1 += w0 * h0.y + w1 * h1v.y + w2 * h2v.y + w3 * h3.y;
    }
    for (; e < end; e++) {
        int s = g_srcsorted[e];
        float xv = g_as2[s];
        float2 hv = *(const float2*)&g_h2[s * 64 + col];
        float v = xv + ad; v = v > 0.f ? v : NEG_SLOPE * v;
        float w = __expf(v);
        sm += w;
        a0 += w * hv.x; a1 += w * hv.y;
    }

    float inv = 1.f / (sm + 1e-16f);
    float v0 = a0 * inv + b2[col], v1 = a1 * inv + b2[col + 1];
    v0 = v0 > 0.f ? v0 : expm1f(v0);
    v1 = v1 > 0.f ? v1 : expm1f(v1);

    float m = fmaxf(v0, v1);
#pragma unroll
    for (int o = 16; o; o >>= 1) m = fmaxf(m, __shfl_xor_sync(0xffffffffu, m, o));
    float es = expf(v0 - m) + expf(v1 - m);
#pragma unroll
    for (int o = 16; o; o >>= 1) es += __shfl_xor_sync(0xffffffffu, es, o);
    float lse = m + logf(es);
    *(float2*)&out[gw * 64 + col] = make_float2(v0 - lse, v1 - lse);
}

// ---------------- launch ----------------
extern "C" void kernel_launch(void* const* d_in, const int* in_sizes, int n_in,
                              void* d_out, int out_size) {
    const float* x      = (const float*)d_in[0];
    const void*  ei     = d_in[1];
    const float* W1     = (const float*)d_in[2];
    const float* a_src1 = (const float*)d_in[3];
    const float* a_dst1 = (const float*)d_in[4];
    const float* b1     = (const float*)d_in[5];
    const float* W2     = (const float*)d_in[6];
    const float* a_src2 = (const float*)d_in[7];
    const float* a_dst2 = (const float*)d_in[8];
    const float* b2     = (const float*)d_in[9];
    float* out = (float*)d_out;

    void *p_flag, *p_deg, *p_h1, *p_x2, *p_h2;
    void *p_as1, *p_ad1, *p_as2, *p_ad2;
    cudaGetSymbolAddress(&p_flag, g_flag32);
    cudaGetSymbolAddress(&p_deg, g_deg);
    cudaGetSymbolAddress(&p_h1, g_h1);
    cudaGetSymbolAddress(&p_x2, g_x2);
    cudaGetSymbolAddress(&p_h2, g_h2);
    cudaGetSymbolAddress(&p_as1, g_as1);
    cudaGetSymbolAddress(&p_ad1, g_ad1);
    cudaGetSymbolAddress(&p_as2, g_as2);
    cudaGetSymbolAddress(&p_ad2, g_ad2);

    cudaMemsetAsync(p_flag, 0, sizeof(int));
    cudaMemsetAsync(p_deg, 0, N_NODES * sizeof(int));

    k_detect<<<1, 256>>>((const unsigned int*)ei);

    // convert || gemm1 (first half)
    k_convert_gemmA<<<G1_A + NCONV, 256>>>(
        ei, x, W1, (float*)p_h1, a_src1, a_dst1, (float*)p_as1, (float*)p_ad1);

    k_scan<<<1, 1024>>>();

    // scatter || gemm1 (second half)
    k_scatter_gemmB<<<G1_B + NCONV, 256>>>(
        x, W1, (float*)p_h1, a_src1, a_dst1, (float*)p_as1, (float*)p_ad1);

    k_agg1<<<(N_NODES * 32 + 255) / 256, 256>>>(b1);

    k_gemm2<<<(N_NODES + 63) / 64, 128>>>(
        (const float*)p_x2, W2, (float*)p_h2, a_src2, a_dst2, (float*)p_as2, (float*)p_ad2);

    k_agg2<<<(N_NODES * 32 + 255) / 256, 256>>>(b2, out);
}

// round 8
// speedup vs baseline: 1.0621x; 1.0621x over previous
#include <cuda_runtime.h>
#include <math.h>

#define N_NODES 30000
#define N_EDGES 480000
#define E_TOT   (N_EDGES + N_NODES)   // 510000 (self-loops appended)
#define NEG_SLOPE 0.2f

// ---------------- device scratch (static, no allocation) ----------------
__device__ int   g_flag32;                 // 1 => edge_index is int32
__device__ int   g_deg[N_NODES];
__device__ int   g_rowptr[N_NODES + 1];
__device__ int   g_src[E_TOT];
__device__ int   g_dst[E_TOT];
__device__ int   g_rank[E_TOT];
__device__ int   g_srcsorted[E_TOT];
__device__ float g_h1[N_NODES * 128];
__device__ float g_as1[N_NODES * 8];
__device__ float g_ad1[N_NODES * 8];
__device__ float g_x2[N_NODES * 128];
__device__ float g_h2[N_NODES * 64];
__device__ float g_as2[N_NODES];
__device__ float g_ad2[N_NODES];

// GEMM1 block split across the two fused kernels (32 nodes per block)
#define G1_BLOCKS ((N_NODES + 31) / 32)        // 938
#define G1_A      (G1_BLOCKS / 2)              // 469 (with convert)
#define G1_B      (G1_BLOCKS - G1_A)           // 469 (with scatter)
#define NCONV     ((E_TOT + 255) / 256)        // 1993

// ---------------- edge dtype detection (sampled, 1 block) ----------------
// int64: odd 32-bit words are high halves of values < 30000 -> all zero.
// int32: odd words are random node indices -> some nonzero among 2048 samples.
__global__ void k_detect(const unsigned int* __restrict__ w) {
    unsigned int acc = 0;
#pragma unroll
    for (int k = 0; k < 8; k++) {
        int s = threadIdx.x * 8 + k;          // 0..2047
        acc |= w[2 * (s * 234) + 1];          // max index 957997 < 960000
    }
    if (acc) atomicOr(&g_flag32, 1);
}

// ---------------- GEMM body (shared by fused + standalone kernels) -------
// H[M,NOUT] = X[M,128] @ W[128,NOUT]; fused alpha epilogue.
// k-loop vectorized by 4: LDS.128 of x + 4x LDG.128 of W per 64 FFMA.
// X loads / H stores use streaming hints so W stays L1-resident.
template <int NOUT, int TY, int NPT, int HEADS>
__device__ __forceinline__ void gemm_body(
    int bid, int tid,
    const float* __restrict__ X, const float* __restrict__ W,
    float* __restrict__ H,
    const float* __restrict__ asrc, const float* __restrict__ adst,
    float* __restrict__ as_out, float* __restrict__ ad_out,
    float (*xs)[128]) {
    constexpr int K  = 128;
    constexpr int TX = NOUT / 4;
    constexpr int MB = TY * NPT;
    constexpr int G  = TX / HEADS;
    int tx = tid % TX, ty = tid / TX;

    int tile0 = bid * MB;
    constexpr int NLOAD = MB * K / 4;
    for (int idx = tid; idx < NLOAD; idx += TX * TY) {
        int r = idx / (K / 4), c = idx % (K / 4);
        float4 v = make_float4(0.f, 0.f, 0.f, 0.f);
        int node = tile0 + r;
        if (node < N_NODES) v = __ldcs(&((const float4*)X)[node * (K / 4) + c]);
        *(float4*)&xs[r][c * 4] = v;
    }
    __syncthreads();

    float4 acc[NPT];
#pragma unroll
    for (int p = 0; p < NPT; p++) acc[p] = make_float4(0.f, 0.f, 0.f, 0.f);
    int jx = tx * 4;
    const float* Wp = W + jx;

#pragma unroll 4
    for (int k4 = 0; k4 < K / 4; k4++) {
        float4 w0 = *(const float4*)(Wp + (4 * k4 + 0) * NOUT);
        float4 w1 = *(const float4*)(Wp + (4 * k4 + 1) * NOUT);
        float4 w2 = *(const float4*)(Wp + (4 * k4 + 2) * NOUT);
        float4 w3 = *(const float4*)(Wp + (4 * k4 + 3) * NOUT);
#pragma unroll
        for (int p = 0; p < NPT; p++) {
            float4 xv = *(const float4*)&xs[ty * NPT + p][4 * k4];
            acc[p].x += w0.x * xv.x; acc[p].y += w0.y * xv.x;
            acc[p].z += w0.z * xv.x; acc[p].w += w0.w * xv.x;
            acc[p].x += w1.x * xv.y; acc[p].y += w1.y * xv.y;
            acc[p].z += w1.z * xv.y; acc[p].w += w1.w * xv.y;
            acc[p].x += w2.x * xv.z; acc[p].y += w2.y * xv.z;
            acc[p].z += w2.z * xv.z; acc[p].w += w2.w * xv.z;
            acc[p].x += w3.x * xv.w; acc[p].y += w3.y * xv.w;
            acc[p].z += w3.z * xv.w; acc[p].w += w3.w * xv.w;
        }
    }

    float4 av = *(const float4*)&asrc[jx];
    float4 bv = *(const float4*)&adst[jx];
    int head = tx / G;
#pragma unroll
    for (int p = 0; p < NPT; p++) {
        int node = tile0 + ty * NPT + p;
        if (node < N_NODES) __stcs((float4*)&H[node * NOUT + jx], acc[p]);
        float s = acc[p].x * av.x + acc[p].y * av.y + acc[p].z * av.z + acc[p].w * av.w;
        float d = acc[p].x * bv.x + acc[p].y * bv.y + acc[p].z * bv.z + acc[p].w * bv.w;
#pragma unroll
        for (int o = 1; o < G; o <<= 1) {
            s += __shfl_xor_sync(0xffffffffu, s, o);
            d += __shfl_xor_sync(0xffffffffu, d, o);
        }
        if ((tx % G) == 0 && node < N_NODES) {
            as_out[node * HEADS + head] = s;
            ad_out[node * HEADS + head] = d;
        }
    }
}

// ---------------- fused: convert (+histogram+rank) || gemm1 first half ----
__global__ __launch_bounds__(256)
void k_convert_gemmA(const void* __restrict__ edges,
                     const float* __restrict__ X, const float* __restrict__ W,
                     float* __restrict__ H,
                     const float* __restrict__ asrc, const float* __restrict__ adst,
                     float* __restrict__ as_out, float* __restrict__ ad_out) {
    __shared__ float xs[32][128];
    if ((int)blockIdx.x < G1_A) {
        gemm_body<128, 8, 4, 8>(blockIdx.x, threadIdx.x, X, W, H,
                                asrc, adst, as_out, ad_out, xs);
        return;
    }
    int i = (blockIdx.x - G1_A) * 256 + threadIdx.x;
    if (i >= E_TOT) return;
    int s, d;
    if (i < N_EDGES) {
        if (g_flag32) {
            const int* p = (const int*)edges;
            s = p[i]; d = p[N_EDGES + i];
        } else {
            const long long* p = (const long long*)edges;
            s = (int)p[i]; d = (int)p[N_EDGES + i];
        }
    } else {
        s = d = i - N_EDGES;
    }
    g_src[i] = s; g_dst[i] = d;
    g_rank[i] = atomicAdd(&g_deg[d], 1);
}

// single-block exclusive scan (30000 elements)
__global__ void k_scan() {
    __shared__ int ss[1024];
    const int CH = (N_NODES + 1023) / 1024;   // 30
    int t = threadIdx.x;
    int base = t * CH;
    int s = 0;
    for (int i = 0; i < CH; i++) {
        int idx = base + i;
        if (idx < N_NODES) s += g_deg[idx];
    }
    ss[t] = s;
    __syncthreads();
    for (int off = 1; off < 1024; off <<= 1) {
        int v = (t >= off) ? ss[t - off] : 0;
        __syncthreads();
        ss[t] += v;
        __syncthreads();
    }
    int run = (t == 0) ? 0 : ss[t - 1];
    for (int i = 0; i < CH; i++) {
        int idx = base + i;
        if (idx < N_NODES) {
            g_rowptr[idx] = run;
            run += g_deg[idx];
        }
    }
    if (t == 0) g_rowptr[N_NODES] = E_TOT;
}

// ---------------- fused: atomic-free scatter || gemm1 second half ---------
__global__ __launch_bounds__(256)
void k_scatter_gemmB(const float* __restrict__ X, const float* __restrict__ W,
                     float* __restrict__ H,
                     const float* __restrict__ asrc, const float* __restrict__ adst,
                     float* __restrict__ as_out, float* __restrict__ ad_out) {
    __shared__ float xs[32][128];
    if ((int)blockIdx.x < G1_B) {
        gemm_body<128, 8, 4, 8>(G1_A + blockIdx.x, threadIdx.x, X, W, H,
                                asrc, adst, as_out, ad_out, xs);
        return;
    }
    int i = (blockIdx.x - G1_B) * 256 + threadIdx.x;
    if (i >= E_TOT) return;
    g_srcsorted[g_rowptr[g_dst[i]] + g_rank[i]] = g_src[i];
}

// ---------------- standalone gemm2 ----------------
__global__ __launch_bounds__(256)
void k_gemm2(const float* __restrict__ X, const float* __restrict__ W,
             float* __restrict__ H,
             const float* __restrict__ asrc, const float* __restrict__ adst,
             float* __restrict__ as_out, float* __restrict__ ad_out) {
    __shared__ float xs[64][128];
    gemm_body<64, 16, 4, 1>(blockIdx.x, threadIdx.x, X, W, H,
                            asrc, adst, as_out, ad_out, xs);
}

// ---------------- layer-1: single-pass softmax + aggregate (warp per dst) -
__global__ void k_agg1(const float* __restrict__ b1) {
    int gw = (blockIdx.x * blockDim.x + threadIdx.x) >> 5;
    int lane = threadIdx.x & 31;
    if (gw >= N_NODES) return;
    int beg = g_rowptr[gw], end = g_rowptr[gw + 1];
    int head = lane >> 2;                 // 4 lanes per head (16 cols/head)
    int col = lane * 4;
    float ad = g_ad1[gw * 8 + head];

    float4 acc = make_float4(0.f, 0.f, 0.f, 0.f);
    float sm = 0.f;
    int e = beg;
    for (; e + 3 < end; e += 4) {
        int s0 = g_srcsorted[e], s1 = g_srcsorted[e + 1];
        int s2 = g_srcsorted[e + 2], s3 = g_srcsorted[e + 3];
        float a0 = g_as1[s0 * 8 + head], a1 = g_as1[s1 * 8 + head];
        float a2 = g_as1[s2 * 8 + head], a3 = g_as1[s3 * 8 + head];
        float4 h0 = *(const float4*)&g_h1[s0 * 128 + col];
        float4 h1v = *(const float4*)&g_h1[s1 * 128 + col];
        float4 h2v = *(const float4*)&g_h1[s2 * 128 + col];
        float4 h3 = *(const float4*)&g_h1[s3 * 128 + col];
        float v0 = a0 + ad; v0 = v0 > 0.f ? v0 : NEG_SLOPE * v0;
        float v1 = a1 + ad; v1 = v1 > 0.f ? v1 : NEG_SLOPE * v1;
        float v2 = a2 + ad; v2 = v2 > 0.f ? v2 : NEG_SLOPE * v2;
        float v3 = a3 + ad; v3 = v3 > 0.f ? v3 : NEG_SLOPE * v3;
        float w0 = __expf(v0), w1 = __expf(v1), w2 = __expf(v2), w3 = __expf(v3);
        sm += (w0 + w1) + (w2 + w3);
        acc.x += w0 * h0.x + w1 * h1v.x + w2 * h2v.x + w3 * h3.x;
        acc.y += w0 * h0.y + w1 * h1v.y + w2 * h2v.y + w3 * h3.y;
        acc.z += w0 * h0.z + w1 * h1v.z + w2 * h2v.z + w3 * h3.z;
        acc.w += w0 * h0.w + w1 * h1v.w + w2 * h2v.w + w3 * h3.w;
    }
    for (; e < end; e++) {
        int s = g_srcsorted[e];
        float a = g_as1[s * 8 + head];
        float4 hv = *(const float4*)&g_h1[s * 128 + col];
        float v = a + ad; v = v > 0.f ? v : NEG_SLOPE * v;
        float w = __expf(v);
        sm += w;
        acc.x += w * hv.x; acc.y += w * hv.y;
        acc.z += w * hv.z; acc.w += w * hv.w;
    }

    float inv = 1.f / (sm + 1e-16f);
    float4 bb = *(const float4*)&b1[col];
    float o0 = acc.x * inv + bb.x, o1 = acc.y * inv + bb.y;
    float o2 = acc.z * inv + bb.z, o3 = acc.w * inv + bb.w;
    o0 = o0 > 0.f ? o0 : expm1f(o0);
    o1 = o1 > 0.f ? o1 : expm1f(o1);
    o2 = o2 > 0.f ? o2 : expm1f(o2);
    o3 = o3 > 0.f ? o3 : expm1f(o3);
    *(float4*)&g_x2[gw * 128 + col] = make_float4(o0, o1, o2, o3);
}

// ---------------- layer-2: single-pass softmax + aggregate + log_softmax --
__global__ void k_agg2(const float* __restrict__ b2, float* __restrict__ out) {
    int gw = (blockIdx.x * blockDim.x + threadIdx.x) >> 5;
    int lane = threadIdx.x & 31;
    if (gw >= N_NODES) return;
    int beg = g_rowptr[gw], end = g_rowptr[gw + 1];
    float ad = g_ad2[gw];
    int col = lane * 2;

    float a0 = 0.f, a1 = 0.f, sm = 0.f;
    int e = beg;
    for (; e + 3 < end; e += 4) {
        int s0 = g_srcsorted[e], s1 = g_srcsorted[e + 1];
        int s2 = g_srcsorted[e + 2], s3 = g_srcsorted[e + 3];
        float x0 = g_as2[s0], x1 = g_as2[s1], x2 = g_as2[s2], x3 = g_as2[s3];
        float2 h0 = *(const float2*)&g_h2[s0 * 64 + col];
        float2 h1v = *(const float2*)&g_h2[s1 * 64 + col];
        float2 h2v = *(const float2*)&g_h2[s2 * 64 + col];
        float2 h3 = *(const float2*)&g_h2[s3 * 64 + col];
        float v0 = x0 + ad; v0 = v0 > 0.f ? v0 : NEG_SLOPE * v0;
        float v1 = x1 + ad; v1 = v1 > 0.f ? v1 : NEG_SLOPE * v1;
        float v2 = x2 + ad; v2 = v2 > 0.f ? v2 : NEG_SLOPE * v2;
        float v3 = x3 + ad; v3 = v3 > 0.f ? v3 : NEG_SLOPE * v3;
        float w0 = __expf(v0), w1 = __expf(v1), w2 = __expf(v2), w3 = __expf(v3);
        sm += (w0 + w1) + (w2 + w3);
        a0 += w0 * h0.x + w1 * h1v.x + w2 * h2v.x + w3 * h3.x;
        a1 += w0 * h0.y + w1 * h1v.y + w2 * h2v.y + w3 * h3.y;
    }
    for (; e < end; e++) {
        int s = g_srcsorted[e];
        float xv = g_as2[s];
        float2 hv = *(const float2*)&g_h2[s * 64 + col];
        float v = xv + ad; v = v > 0.f ? v : NEG_SLOPE * v;
        float w = __expf(v);
        sm += w;
        a0 += w * hv.x; a1 += w * hv.y;
    }

    float inv = 1.f / (sm + 1e-16f);
    float v0 = a0 * inv + b2[col], v1 = a1 * inv + b2[col + 1];
    v0 = v0 > 0.f ? v0 : expm1f(v0);
    v1 = v1 > 0.f ? v1 : expm1f(v1);

    float m = fmaxf(v0, v1);
#pragma unroll
    for (int o = 16; o; o >>= 1) m = fmaxf(m, __shfl_xor_sync(0xffffffffu, m, o));
    float es = expf(v0 - m) + expf(v1 - m);
#pragma unroll
    for (int o = 16; o; o >>= 1) es += __shfl_xor_sync(0xffffffffu, es, o);
    float lse = m + logf(es);
    *(float2*)&out[gw * 64 + col] = make_float2(v0 - lse, v1 - lse);
}

// ---------------- launch ----------------
extern "C" void kernel_launch(void* const* d_in, const int* in_sizes, int n_in,
                              void* d_out, int out_size) {
    const float* x      = (const float*)d_in[0];
    const void*  ei     = d_in[1];
    const float* W1     = (const float*)d_in[2];
    const float* a_src1 = (const float*)d_in[3];
    const float* a_dst1 = (const float*)d_in[4];
    const float* b1     = (const float*)d_in[5];
    const float* W2     = (const float*)d_in[6];
    const float* a_src2 = (const float*)d_in[7];
    const float* a_dst2 = (const float*)d_in[8];
    const float* b2     = (const float*)d_in[9];
    float* out = (float*)d_out;

    void *p_flag, *p_deg, *p_h1, *p_x2, *p_h2;
    void *p_as1, *p_ad1, *p_as2, *p_ad2;
    cudaGetSymbolAddress(&p_flag, g_flag32);
    cudaGetSymbolAddress(&p_deg, g_deg);
    cudaGetSymbolAddress(&p_h1, g_h1);
    cudaGetSymbolAddress(&p_x2, g_x2);
    cudaGetSymbolAddress(&p_h2, g_h2);
    cudaGetSymbolAddress(&p_as1, g_as1);
    cudaGetSymbolAddress(&p_ad1, g_ad1);
    cudaGetSymbolAddress(&p_as2, g_as2);
    cudaGetSymbolAddress(&p_ad2, g_ad2);

    cudaMemsetAsync(p_flag, 0, sizeof(int));
    cudaMemsetAsync(p_deg, 0, N_NODES * sizeof(int));

    k_detect<<<1, 256>>>((const unsigned int*)ei);

    // convert || gemm1 (first half)
    k_convert_gemmA<<<G1_A + NCONV, 256>>>(
        ei, x, W1, (float*)p_h1, a_src1, a_dst1, (float*)p_as1, (float*)p_ad1);

    k_scan<<<1, 1024>>>();

    // scatter || gemm1 (second half)
    k_scatter_gemmB<<<G1_B + NCONV, 256>>>(
        x, W1, (float*)p_h1, a_src1, a_dst1, (float*)p_as1, (float*)p_ad1);

    k_agg1<<<(N_NODES * 32 + 255) / 256, 256>>>(b1);

    k_gemm2<<<(N_NODES + 63) / 64, 256>>>(
        (const float*)p_x2, W2, (float*)p_h2, a_src2, a_dst2, (float*)p_as2, (float*)p_ad2);

    k_agg2<<<(N_NODES * 32 + 255) / 256, 256>>>(b2, out);
}